// round 16
// baseline (speedup 1.0000x reference)
#include <cuda_runtime.h>
#include <cuda_bf16.h>

#define MODIFIER_COL 11
#define OWNER_COL    24
#define MAXG         8192
#define F_DIM        128
#define WAITER_BLOCKS 8

// One 16B slot per graph: {count, s0, s1, 0}. Every head's contribution rides
// ONE relaxed no-return v4 RED on this address; L2 same-address serialization
// means count==expected implies ALL components are complete. No fences,
// acquires, returns, or markers anywhere.
// Zero-initialized at load; waiters reset consumed slots for the next replay.
__device__ float4 g_state[MAXG];

__device__ __forceinline__ void red_add_v4_relaxed(float4* p, float4 d)
{
    asm volatile(
        "red.relaxed.gpu.global.add.v4.f32 [%0], {%1,%2,%3,%4};"
        :: "l"(p), "f"(d.x), "f"(d.y), "f"(d.z), "f"(d.w) : "memory");
}

__device__ __forceinline__ float4 ld_volatile_v4(const float4* p)
{
    float4 v;
    asm volatile("ld.volatile.global.v4.f32 {%0,%1,%2,%3}, [%4];"
                 : "=f"(v.x), "=f"(v.y), "=f"(v.z), "=f"(v.w)
                 : "l"(p) : "memory");
    return v;
}

// Single kernel. Blocks [0, WAITER_BLOCKS): one waiter thread per graph —
// binary-searches its expected count (overlapped with the reduce), polls its
// slot, runs the MLP. Remaining blocks: R2's segreduce, ONE v4 RED per head.
__global__ __launch_bounds__(256) void fused_kernel(
    const float* __restrict__ nf,
    const int*   __restrict__ batch,
    const float* __restrict__ W1,   // [32,2] row-major
    const float* __restrict__ b1,   // [32]
    const float* __restrict__ W2,   // [1,32]
    const float* __restrict__ b2,   // [1]
    float* __restrict__ out,
    int N, int G)
{
    if (blockIdx.x < WAITER_BLOCKS) {
        // ------------------------------ waiter ------------------------------
        __shared__ float sW1[64];
        __shared__ float sb1[32];
        __shared__ float sW2[32];
        __shared__ float sb2;

        const int t = threadIdx.x;
        if (t < 64)        sW1[t]      = W1[t];
        else if (t < 96)   sb1[t - 64] = b1[t - 64];
        else if (t < 128)  sW2[t - 96] = W2[t - 96];
        if (t == 0)        sb2 = *b2;
        __syncthreads();

        int g = blockIdx.x * blockDim.x + t;
        if (g >= G || g >= MAXG) return;

        // Expected count via two binary searches on the sorted keys
        // (runs concurrently with the reduce's streaming phase).
        int lo = 0, hi = N;
        while (lo < hi) { int m = (lo + hi) >> 1;
                          if (__ldg(batch + m) < g) lo = m + 1; else hi = m; }
        int start = lo;
        hi = N;
        while (lo < hi) { int m = (lo + hi) >> 1;
                          if (__ldg(batch + m) < g + 1) lo = m + 1; else hi = m; }
        int cnt = lo - start;

        if (cnt == 0) { out[g] = 0.f; return; }     // empty graph

        float fc = (float)cnt;                       // < 2^24: exact
        float4 s;
        while (true) {
            s = ld_volatile_v4(&g_state[g]);
            if (s.x == fc) break;                    // all contributions landed
            __nanosleep(100);
        }
        g_state[g] = make_float4(0.f, 0.f, 0.f, 0.f);   // reset for replay

        float f0 = 1.f - s.y / fc;
        float f1 = 1.f - s.z / fc;
        float acc = sb2;
        #pragma unroll
        for (int j = 0; j < 32; ++j) {
            float h = fmaf(f0, sW1[2 * j], fmaf(f1, sW1[2 * j + 1], sb1[j]));
            h   = fmaxf(h, 0.f);
            acc = fmaf(sW2[j], h, acc);
        }
        out[g] = 1.f / (1.f + __expf(-acc));
        return;
    }

    // ------------------------- reduce (R2 hot path) -------------------------
    const int i    = (blockIdx.x - WAITER_BLOCKS) * blockDim.x + threadIdx.x;
    const int lane = threadIdx.x & 31;

    int   g  = -1;
    float c  = 0.f, v0 = 0.f, v1 = 0.f;
    if (i < N) {
        g  = batch[i];
        const float* row = nf + (size_t)i * F_DIM;
        v0 = __ldg(row + MODIFIER_COL);
        v1 = __ldg(row + OWNER_COL);
        c  = 1.f;
    }

    // Down-sweep segmented reduction (keys non-decreasing across lanes).
    #pragma unroll
    for (int d = 1; d < 32; d <<= 1) {
        int   go = __shfl_down_sync(0xffffffffu, g,  d);
        float co = __shfl_down_sync(0xffffffffu, c,  d);
        float a0 = __shfl_down_sync(0xffffffffu, v0, d);
        float a1 = __shfl_down_sync(0xffffffffu, v1, d);
        if (lane + d < 32 && go == g) { c += co; v0 += a0; v1 += a1; }
    }

    int  gprev = __shfl_up_sync(0xffffffffu, g, 1);
    bool head  = (lane == 0) || (gprev != g);
    if (head && g >= 0 && g < MAXG)
        red_add_v4_relaxed(&g_state[g], make_float4(c, v0, v1, 0.f));
}

extern "C" void kernel_launch(void* const* d_in, const int* in_sizes, int n_in,
                              void* d_out, int out_size)
{
    // order: node_features, batch, graph_embedding, W1, b1, W2, b2
    const float* nf    = (const float*)d_in[0];
    const int*   batch = (const int*)d_in[1];
    const float* W1    = (const float*)d_in[3];
    const float* b1    = (const float*)d_in[4];
    const float* W2    = (const float*)d_in[5];
    const float* b2    = (const float*)d_in[6];
    float*       out   = (float*)d_out;

    int N = in_sizes[1];
    int G = in_sizes[2] / F_DIM;
    if (G <= 0 || G > MAXG) G = out_size;

    int rb = (N + 255) / 256;
    fused_kernel<<<WAITER_BLOCKS + rb, 256>>>(nf, batch, W1, b1, W2, b2, out, N, G);
}